// round 10
// baseline (speedup 1.0000x reference)
#include <cuda_runtime.h>
#include <cuda_bf16.h>
#include <cstdint>

// x[4096,2048] @ W_enc[2048,16384] + b_enc -> z ; abs-top-64 -> z_sparse ;
// z_sparse @ W_dec[16384,2048] + b_dec -> recon.
// Output: recon [B,D] then z_sparse [B,L], fp32.

#define BSZ   4096
#define DDIM  2048
#define LDIM  16384
#define KSEL  64

// ---------------- scratch (no allocs allowed -> __device__ globals) ----------
__device__ float    g_z[(size_t)BSZ * LDIM];      // dense pre-activation z (256 MB)
__device__ int      g_tidx[BSZ * KSEL];
__device__ float    g_tval[BSZ * KSEL];
// pre-split operands (written once per launch by presplit kernels)
__device__ uint32_t g_whi[(size_t)DDIM * LDIM];           // tf32(w_hi)   128 MB
__device__ uint32_t g_whb[(size_t)(DDIM / 2) * LDIM];     // bf16x2(w_hi)  67 MB
__device__ uint32_t g_wlb[(size_t)(DDIM / 2) * LDIM];     // bf16x2(w_lo)  67 MB
__device__ uint32_t g_xhi[(size_t)BSZ * DDIM];            // tf32(x_hi)
__device__ uint32_t g_xhb[(size_t)BSZ * DDIM / 2];        // bf16x2(x_hi)
__device__ uint32_t g_xlb[(size_t)BSZ * DDIM / 2];        // bf16x2(x_lo)

// ===================== helpers ===============================================
__device__ __forceinline__ uint32_t smem_u32(const void* p) {
    uint32_t a;
    asm("{ .reg .u64 t; cvta.to.shared.u64 t, %1; cvt.u32.u64 %0, t; }"
        : "=r"(a) : "l"(p));
    return a;
}
// hi = round-to-nearest tf32(x); lo = tf32(x - hi). hi+lo error ~2^-24 |x|.
__device__ __forceinline__ void split_tf32(float x, uint32_t& hi, uint32_t& lo) {
    asm("cvt.rna.tf32.f32 %0, %1;" : "=r"(hi) : "f"(x));
    float r = x - __uint_as_float(hi);
    asm("cvt.rna.tf32.f32 %0, %1;" : "=r"(lo) : "f"(r));
}
// pack two floats as bf16x2: low half = f_even (lower k), high = f_odd
__device__ __forceinline__ uint32_t pack_bf16(float f_even, float f_odd) {
    uint32_t r;
    asm("cvt.rn.bf16x2.f32 %0, %1, %2;" : "=r"(r) : "f"(f_odd), "f"(f_even));
    return r;
}
__device__ __forceinline__ void cp16(uint32_t dst, const void* src) {
    asm volatile("cp.async.cg.shared.global [%0], [%1], 16;"
                 :: "r"(dst), "l"(src) : "memory");
}
#define CP_COMMIT() asm volatile("cp.async.commit_group;" ::: "memory")
#define CP_WAIT(n)  asm volatile("cp.async.wait_group %0;" :: "n"(n) : "memory")

#define MMA_TF32(d, a, b)                                                  \
    asm volatile("mma.sync.aligned.m16n8k8.row.col.f32.tf32.tf32.f32 "     \
                 "{%0,%1,%2,%3}, {%4,%5,%6,%7}, {%8,%9}, {%0,%1,%2,%3};"   \
                 : "+f"((d)[0]), "+f"((d)[1]), "+f"((d)[2]), "+f"((d)[3])  \
                 : "r"((a)[0]), "r"((a)[1]), "r"((a)[2]), "r"((a)[3]),     \
                   "r"((b)[0]), "r"((b)[1]))

#define MMA_BF16(d, a, b)                                                  \
    asm volatile("mma.sync.aligned.m16n8k16.row.col.f32.bf16.bf16.f32 "    \
                 "{%0,%1,%2,%3}, {%4,%5,%6,%7}, {%8,%9}, {%0,%1,%2,%3};"   \
                 : "+f"((d)[0]), "+f"((d)[1]), "+f"((d)[2]), "+f"((d)[3])  \
                 : "r"((a)[0]), "r"((a)[1]), "r"((a)[2]), "r"((a)[3]),     \
                   "r"((b)[0]), "r"((b)[1]))

// ===================== pre-split kernels =====================================
__global__ __launch_bounds__(256)
void presplit_w(const float* __restrict__ W) {
    const size_t total = (size_t)(DDIM / 2) * (LDIM / 4);
    const size_t stride = (size_t)gridDim.x * blockDim.x;
    for (size_t idx = (size_t)blockIdx.x * blockDim.x + threadIdx.x;
         idx < total; idx += stride) {
        const size_t kw = idx / (LDIM / 4);
        const size_t nq = idx % (LDIM / 4);
        const size_t n = nq * 4;
        const size_t r0 = (2 * kw) * (size_t)LDIM + n;
        const size_t r1 = r0 + LDIM;
        float4 v0 = *(const float4*)(W + r0);
        float4 v1 = *(const float4*)(W + r1);
        uint4 h0, l0, h1, l1;
        split_tf32(v0.x, h0.x, l0.x); split_tf32(v0.y, h0.y, l0.y);
        split_tf32(v0.z, h0.z, l0.z); split_tf32(v0.w, h0.w, l0.w);
        split_tf32(v1.x, h1.x, l1.x); split_tf32(v1.y, h1.y, l1.y);
        split_tf32(v1.z, h1.z, l1.z); split_tf32(v1.w, h1.w, l1.w);
        *(uint4*)(g_whi + r0) = h0;
        *(uint4*)(g_whi + r1) = h1;
        uint4 hb, lb;
        hb.x = pack_bf16(__uint_as_float(h0.x), __uint_as_float(h1.x));
        hb.y = pack_bf16(__uint_as_float(h0.y), __uint_as_float(h1.y));
        hb.z = pack_bf16(__uint_as_float(h0.z), __uint_as_float(h1.z));
        hb.w = pack_bf16(__uint_as_float(h0.w), __uint_as_float(h1.w));
        lb.x = pack_bf16(__uint_as_float(l0.x), __uint_as_float(l1.x));
        lb.y = pack_bf16(__uint_as_float(l0.y), __uint_as_float(l1.y));
        lb.z = pack_bf16(__uint_as_float(l0.z), __uint_as_float(l1.z));
        lb.w = pack_bf16(__uint_as_float(l0.w), __uint_as_float(l1.w));
        *(uint4*)(g_whb + kw * (size_t)LDIM + n) = hb;
        *(uint4*)(g_wlb + kw * (size_t)LDIM + n) = lb;
    }
}
__global__ __launch_bounds__(256)
void presplit_x(const float* __restrict__ X) {
    const size_t n = (size_t)BSZ * DDIM;
    const size_t stride = (size_t)gridDim.x * blockDim.x * 4;
    for (size_t i = ((size_t)blockIdx.x * blockDim.x + threadIdx.x) * 4;
         i < n; i += stride) {
        float4 v = *(const float4*)(X + i);
        uint4 h, l;
        split_tf32(v.x, h.x, l.x); split_tf32(v.y, h.y, l.y);
        split_tf32(v.z, h.z, l.z); split_tf32(v.w, h.w, l.w);
        *(uint4*)(g_xhi + i) = h;
        uint2 hp, lp;
        hp.x = pack_bf16(__uint_as_float(h.x), __uint_as_float(h.y));
        hp.y = pack_bf16(__uint_as_float(h.z), __uint_as_float(h.w));
        lp.x = pack_bf16(__uint_as_float(l.x), __uint_as_float(l.y));
        lp.y = pack_bf16(__uint_as_float(l.z), __uint_as_float(l.w));
        *(uint2*)(g_xhb + i / 2) = hp;
        *(uint2*)(g_xlb + i / 2) = lp;
    }
}

// ======================= Encode: tf32-hh + bf16 corrections ==================
// CTA 128M x 128N, KC=32 k/chunk. R10: 512 threads, 16 warps as 4(m) x 4(n),
// warp tile 32x32 -- 4 warps/SMSP so fragment-LDS latency hides under other
// warps' MMA streams (R9 had 8 warps / 1 CTA and serialized LDS vs tensor).
// Numerics identical to passing R9: per-chunk zeroed d2, IEEE fold into d.
#define BME 128
#define BNE 128
#define KCE 32
#define NCH (DDIM / KCE)        // 64
// stage layout in 32-bit words
#define O_AH2  0                // tf32 A hi: 4096 w, m*32 + 4*(q^(m&7))
#define O_BH2  4096             // tf32 B hi: 4096 w, kb*128 + 4*(nq^(2*(kb&3)))
#define O_XHB  8192             // bf16 A hi: 128 rows * pitch 20 = 2560 w
#define O_XLB  10752            // bf16 A lo: 2560 w
#define O_WLB  13312            // bf16 B lo: 16*128 = 2048 w, kw*128 + (n^(8*(kw&3)))
#define O_WHB  15360            // bf16 B hi: 2048 w
#define STG_W  17408
#define NSTG 3
#define ENC_SMEM (NSTG * STG_W * 4)   // 208896 bytes
#define APITCH 20
#define ETHREADS 512

__global__ __launch_bounds__(ETHREADS, 1)
void encode_mma(const float* __restrict__ bias)  // b_enc [N]
{
    extern __shared__ uint32_t sm[];
    const uint32_t sbase = smem_u32(sm);
    const int tid  = threadIdx.x;
    const int lane = tid & 31, wid = tid >> 5;
    const int wm = wid & 3;          // 0..3 -> m offset 0/32/64/96
    const int wn = wid >> 2;         // 0..3 -> n offset 0/32/64/96
    const int g   = lane >> 2;       // 0..7
    const int tig = lane & 3;        // 0..3
    const int m0 = blockIdx.x * BME; // M-fast grid: W tile shared across CTAs
    const int n0 = blockIdx.y * BNE;

    float d[2][4][4];                // warp tile 32m x 32n
#pragma unroll
    for (int mi = 0; mi < 2; mi++)
#pragma unroll
        for (int ni = 0; ni < 4; ni++)
#pragma unroll
            for (int q = 0; q < 4; q++) d[mi][ni][q] = 0.0f;

    // ---- issue one chunk's 8 cp.async per thread (512 threads) ----
    auto issue_chunk = [&](int c) {
        const int k0 = c * KCE;
        const int kw0 = c * (KCE / 2);
        const uint32_t st = sbase + (uint32_t)(c % NSTG) * (STG_W * 4);
#pragma unroll
        for (int i = 0; i < 2; i++) {   // tf32 hi tiles: 2 + 2 cp16
            const int gq = tid + ETHREADS * i;      // 0..1023
            const int m = gq >> 3, q = gq & 7;
            cp16(st + (uint32_t)(O_AH2 + m * 32 + 4 * (q ^ (m & 7))) * 4,
                 g_xhi + (size_t)(m0 + m) * DDIM + k0 + q * 4);
            const int kb = gq >> 5, nq = gq & 31;
            cp16(st + (uint32_t)(O_BH2 + kb * 128 + 4 * (nq ^ (2 * (kb & 3)))) * 4,
                 g_whi + (size_t)(k0 + kb) * LDIM + n0 + nq * 4);
        }
        {   // bf16 tiles: 1 cp16 each of 4 arrays
            const int gq = tid;                      // 0..511
            const int m = gq >> 2, q = gq & 3;
            const uint32_t da = (uint32_t)(m * APITCH + 4 * q);
            const size_t sa = (size_t)(m0 + m) * (DDIM / 2) + kw0 + q * 4;
            cp16(st + (O_XHB + da) * 4, g_xhb + sa);
            cp16(st + (O_XLB + da) * 4, g_xlb + sa);
            const int kw = gq >> 5, nq = gq & 31;
            const uint32_t wo = (uint32_t)(kw * 128 + ((4 * nq) ^ (8 * (kw & 3))));
            const size_t sw = (size_t)(kw0 + kw) * LDIM + n0 + nq * 4;
            cp16(st + (O_WLB + wo) * 4, g_wlb + sw);
            cp16(st + (O_WHB + wo) * 4, g_whb + sw);
        }
    };

    // ---- consumer ----
    auto mma_chunk = [&](int stg) {
        const int base = stg * STG_W;
        float d2[2][4][4];
#pragma unroll
        for (int mi = 0; mi < 2; mi++)
#pragma unroll
            for (int ni = 0; ni < 4; ni++)
#pragma unroll
                for (int q = 0; q < 4; q++) d2[mi][ni][q] = 0.0f;

        // --- tf32 hh: 4 k8-steps ---
#pragma unroll
        for (int ks = 0; ks < 4; ks++) {
            const int x0 = 4 * ((2 * ks) ^ g);
            const int x1 = 4 * ((2 * ks + 1) ^ g);
            uint32_t ah[2][4];
#pragma unroll
            for (int mi = 0; mi < 2; mi++) {
                const int mrow = wm * 32 + mi * 16 + g;
                const int rb = base + mrow * 32 + tig;
                ah[mi][0] = sm[O_AH2 + rb + x0];
                ah[mi][1] = sm[O_AH2 + rb + 256 + x0];   // row +8
                ah[mi][2] = sm[O_AH2 + rb + x1];         // k +4
                ah[mi][3] = sm[O_AH2 + rb + 256 + x1];
            }
            const int kk = ks * 8 + tig;
            const int krow = base + kk * 128 + (g & 3);
            uint32_t bh[4][2];
#pragma unroll
            for (int ni = 0; ni < 4; ni++) {
                const int nsw = 4 * ((wn * 8 + ni * 2 + (g >> 2)) ^ (2 * tig));
                bh[ni][0] = sm[O_BH2 + krow + nsw];
                bh[ni][1] = sm[O_BH2 + krow + 512 + nsw];   // k +4
            }
#pragma unroll
            for (int mi = 0; mi < 2; mi++)
#pragma unroll
                for (int ni = 0; ni < 4; ni++)
                    MMA_TF32(d2[mi][ni], ah[mi], bh[ni]);
        }

        // --- bf16 corrections: 2 k16-steps ---
#pragma unroll
        for (int s = 0; s < 2; s++) {
            const int kwA0 = 8 * s + tig;
            const int kwA1 = kwA0 + 4;
            uint32_t axh[2][4], axl[2][4];
#pragma unroll
            for (int mi = 0; mi < 2; mi++) {
                const int arow = base + (wm * 32 + mi * 16 + g) * APITCH;
                axh[mi][0] = sm[O_XHB + arow + kwA0];
                axh[mi][1] = sm[O_XHB + arow + 8 * APITCH + kwA0];  // row +8
                axh[mi][2] = sm[O_XHB + arow + kwA1];
                axh[mi][3] = sm[O_XHB + arow + 8 * APITCH + kwA1];
                axl[mi][0] = sm[O_XLB + arow + kwA0];
                axl[mi][1] = sm[O_XLB + arow + 8 * APITCH + kwA0];
                axl[mi][2] = sm[O_XLB + arow + kwA1];
                axl[mi][3] = sm[O_XLB + arow + 8 * APITCH + kwA1];
            }
            const int kwB0 = 8 * s + tig;
            const int kwB1 = kwB0 + 4;
            uint32_t bwl[4][2], bwh[4][2];
#pragma unroll
            for (int ni = 0; ni < 4; ni++) {
                const int ncol = wn * 32 + ni * 8 + g;
                const int w0 = base + kwB0 * 128 + (ncol ^ (8 * (kwB0 & 3)));
                const int w1 = base + kwB1 * 128 + (ncol ^ (8 * (kwB1 & 3)));
                bwl[ni][0] = sm[O_WLB + w0];
                bwl[ni][1] = sm[O_WLB + w1];
                bwh[ni][0] = sm[O_WHB + w0];
                bwh[ni][1] = sm[O_WHB + w1];
            }
#pragma unroll
            for (int mi = 0; mi < 2; mi++)
#pragma unroll
                for (int ni = 0; ni < 4; ni++) {
                    MMA_BF16(d2[mi][ni], axh[mi], bwl[ni]);
                    MMA_BF16(d2[mi][ni], axl[mi], bwh[ni]);
                }
        }

        // IEEE-RN fold of chunk partial into main accumulator
#pragma unroll
        for (int mi = 0; mi < 2; mi++)
#pragma unroll
            for (int ni = 0; ni < 4; ni++)
#pragma unroll
                for (int q = 0; q < 4; q++)
                    d[mi][ni][q] += d2[mi][ni][q];
    };

    // ---- 3-stage pipeline ----
    issue_chunk(0); CP_COMMIT();
    issue_chunk(1); CP_COMMIT();
    for (int c = 0; c < NCH; c++) {
        if (c + 2 < NCH) { CP_WAIT(1); } else { CP_WAIT(0); }
        __syncthreads();
        if (c + 2 < NCH) { issue_chunk(c + 2); CP_COMMIT(); }
        mma_chunk(c % NSTG);
    }

    // ---- epilogue: add bias, write z ----
#pragma unroll
    for (int ni = 0; ni < 4; ni++) {
        const int col = n0 + wn * 32 + ni * 8 + 2 * tig;
        const float b0 = bias[col], b1 = bias[col + 1];
#pragma unroll
        for (int mi = 0; mi < 2; mi++) {
            const int r0 = m0 + wm * 32 + mi * 16 + g;
            float2 v0 = make_float2(d[mi][ni][0] + b0, d[mi][ni][1] + b1);
            float2 v1 = make_float2(d[mi][ni][2] + b0, d[mi][ni][3] + b1);
            *(float2*)(g_z + (size_t)r0 * LDIM + col) = v0;
            *(float2*)(g_z + (size_t)(r0 + 8) * LDIM + col) = v1;
        }
    }
}

// ---------------- Kernel 2: abs-top-64, threshold-compact + exact radix ------
#define TCAP 2048
#define EQCAP 128

__global__ __launch_bounds__(256)
void topk_select(float* __restrict__ zs_out)
{
    __shared__ uint32_t s_bits[TCAP];
    __shared__ int      s_gidx[TCAP];
    __shared__ unsigned int hist[256];
    __shared__ unsigned int s_cnt, s_prefix, s_remaining, s_cntGT, s_eqcnt;
    __shared__ int   selIdx[KSEL];
    __shared__ float selVal[KSEL];
    __shared__ int   eqPos[EQCAP];

    const int row = blockIdx.x;
    const int tid = threadIdx.x;
    const float* zrow  = g_z    + (size_t)row * LDIM;
    float*       zsrow = zs_out + (size_t)row * LDIM;

    if (tid == 0) s_cnt = 0u;
    __syncthreads();

    const unsigned int T0 = 0x40133333u;   // bits of 2.3f
    for (int i = tid * 4; i < LDIM; i += 1024) {
        float4 v = *(const float4*)(zrow + i);
        *(float4*)(zsrow + i) = make_float4(0.f, 0.f, 0.f, 0.f);
        uint32_t b[4] = {__float_as_uint(v.x), __float_as_uint(v.y),
                         __float_as_uint(v.z), __float_as_uint(v.w)};
#pragma unroll
        for (int j = 0; j < 4; j++) {
            if ((b[j] & 0x7fffffffu) >= T0) {
                unsigned int p = atomicAdd(&s_cnt, 1u);
                if (p < TCAP) { s_bits[p] = b[j]; s_gidx[p] = i + j; }
            }
        }
    }
    __syncthreads();

    const unsigned int C = min(s_cnt, (unsigned int)TCAP);
    bool fallback = (s_cnt < (unsigned int)KSEL) || (s_cnt > (unsigned int)TCAP);
    unsigned int T = 0u, needEQ = 0u;

    if (!fallback) {
        if (tid == 0) { s_prefix = 0u; s_remaining = KSEL; }
        __syncthreads();
#pragma unroll
        for (int pass = 0; pass < 4; pass++) {
            const int shift = 24 - pass * 8;
            if (tid < 256) hist[tid] = 0u;
            __syncthreads();
            const unsigned int pfx = s_prefix;
            for (unsigned int i = tid; i < C; i += 256) {
                unsigned int key = s_bits[i] & 0x7fffffffu;
                bool in = (pass == 0) || ((key >> (shift + 8)) == pfx);
                if (in) atomicAdd(&hist[(key >> shift) & 255u], 1u);
            }
            __syncthreads();
            if (tid == 0) {
                unsigned int cum = 0u; int bkt = 255;
                for (; bkt > 0; bkt--) {
                    unsigned int cc = hist[bkt];
                    if (cum + cc >= s_remaining) break;
                    cum += cc;
                }
                s_prefix = (pfx << 8) | (unsigned int)bkt;
                s_remaining -= cum;
            }
            __syncthreads();
        }
        T = s_prefix; needEQ = s_remaining;

        if (tid == 0) { s_cntGT = 0u; s_eqcnt = 0u; }
        __syncthreads();
        for (unsigned int i = tid; i < C; i += 256) {
            unsigned int key = s_bits[i] & 0x7fffffffu;
            if (key > T) {
                unsigned int p = atomicAdd(&s_cntGT, 1u);
                selIdx[p] = s_gidx[i];
                selVal[p] = __uint_as_float(s_bits[i]);
            } else if (key == T) {
                unsigned int p = atomicAdd(&s_eqcnt, 1u);
                if (p < EQCAP) eqPos[p] = (int)i;
            }
        }
        __syncthreads();
        if (s_eqcnt > (unsigned int)EQCAP) {
            fallback = true;
        } else if (tid == 0) {
            const unsigned int base = s_cntGT;   // == KSEL - needEQ
            const int m = (int)s_eqcnt;
            for (unsigned int t = 0; t < needEQ; t++) {
                int bj = 0, bidx = 0x7fffffff;
                for (int j = 0; j < m; j++) {
                    const int pos = eqPos[j];
                    if (pos >= 0 && s_gidx[pos] < bidx) { bidx = s_gidx[pos]; bj = j; }
                }
                selIdx[base + t] = s_gidx[eqPos[bj]];
                selVal[base + t] = __uint_as_float(s_bits[eqPos[bj]]);
                eqPos[bj] = -1;
            }
        }
        __syncthreads();
    }

    if (fallback) {
        if (tid == 0) { s_prefix = 0u; s_remaining = KSEL; }
        __syncthreads();
#pragma unroll
        for (int pass = 0; pass < 4; pass++) {
            const int shift = 24 - pass * 8;
            if (tid < 256) hist[tid] = 0u;
            __syncthreads();
            const unsigned int pfx = s_prefix;
            for (int i = tid; i < LDIM; i += 256) {
                unsigned int key = __float_as_uint(zrow[i]) & 0x7fffffffu;
                bool in = (pass == 0) || ((key >> (shift + 8)) == pfx);
                if (in) atomicAdd(&hist[(key >> shift) & 255u], 1u);
            }
            __syncthreads();
            if (tid == 0) {
                unsigned int cum = 0u; int bkt = 255;
                for (; bkt > 0; bkt--) {
                    unsigned int cc = hist[bkt];
                    if (cum + cc >= s_remaining) break;
                    cum += cc;
                }
                s_prefix = (pfx << 8) | (unsigned int)bkt;
                s_remaining -= cum;
            }
            __syncthreads();
        }
        T = s_prefix; needEQ = s_remaining;

        if (tid == 0) s_cntGT = 0u;
        __syncthreads();
        for (int i = tid; i < LDIM; i += 256) {
            unsigned int bb = __float_as_uint(zrow[i]);
            unsigned int key = bb & 0x7fffffffu;
            if (key > T) {
                unsigned int p = atomicAdd(&s_cntGT, 1u);
                selIdx[p] = i;
                selVal[p] = __uint_as_float(bb);
            }
        }
        __syncthreads();
        if (tid < 32) {
            const unsigned int base = s_cntGT;
            unsigned int taken = 0u;
            for (int i0 = 0; i0 < LDIM && taken < needEQ; i0 += 32) {
                const int i = i0 + tid;
                unsigned int bb = __float_as_uint(zrow[i]);
                unsigned int key = bb & 0x7fffffffu;
                bool eq = (key == T);
                unsigned int msk = __ballot_sync(0xffffffffu, eq);
                if (eq) {
                    unsigned int rank = __popc(msk & ((1u << tid) - 1u));
                    if (taken + rank < needEQ) {
                        selIdx[base + taken + rank] = i;
                        selVal[base + taken + rank] = __uint_as_float(bb);
                    }
                }
                taken += __popc(msk);
            }
        }
        __syncthreads();
    }

    if (tid < KSEL) {
        zsrow[selIdx[tid]] = selVal[tid];
        g_tidx[row * KSEL + tid] = selIdx[tid];
        g_tval[row * KSEL + tid] = selVal[tid];
    }
}

// ---------------- Kernel 3: sparse decode ------------------------------------
__global__ __launch_bounds__(256)
void decode_sparse(const float* __restrict__ Wd,
                   const float* __restrict__ bd,
                   float* __restrict__ recon)
{
    __shared__ int   sIdx[KSEL];
    __shared__ float sVal[KSEL];
    const int row = blockIdx.x;
    const int tid = threadIdx.x;
    if (tid < KSEL) {
        sIdx[tid] = g_tidx[row * KSEL + tid];
        sVal[tid] = g_tval[row * KSEL + tid];
    }
    __syncthreads();

    const int c0 = tid * 4;
    const int c1 = (tid + 256) * 4;
    float4 a0 = *(const float4*)(bd + c0);
    float4 a1 = *(const float4*)(bd + c1);

#pragma unroll 4
    for (int j = 0; j < KSEL; j++) {
        const float v = sVal[j];
        const float* wr = Wd + (size_t)sIdx[j] * DDIM;
        float4 w0 = *(const float4*)(wr + c0);
        float4 w1 = *(const float4*)(wr + c1);
        a0.x = fmaf(v, w0.x, a0.x); a0.y = fmaf(v, w0.y, a0.y);
        a0.z = fmaf(v, w0.z, a0.z); a0.w = fmaf(v, w0.w, a0.w);
        a1.x = fmaf(v, w1.x, a1.x); a1.y = fmaf(v, w1.y, a1.y);
        a1.z = fmaf(v, w1.z, a1.z); a1.w = fmaf(v, w1.w, a1.w);
    }
    float* r = recon + (size_t)row * DDIM;
    *(float4*)(r + c0) = a0;
    *(float4*)(r + c1) = a1;
}

// ---------------- launch ------------------------------------------------------
extern "C" void kernel_launch(void* const* d_in, const int* in_sizes, int n_in,
                              void* d_out, int out_size)
{
    const float* x     = (const float*)d_in[0];   // [B, D]
    const float* W_enc = (const float*)d_in[1];   // [D, L]
    const float* b_enc = (const float*)d_in[2];   // [L]
    const float* W_dec = (const float*)d_in[3];   // [L, D]
    const float* b_dec = (const float*)d_in[4];   // [D]
    (void)in_sizes; (void)n_in; (void)out_size;

    float* recon = (float*)d_out;                          // [B, D]
    float* zs    = (float*)d_out + (size_t)BSZ * DDIM;     // [B, L]

    // 0) one-time operand pre-split (~90us)
    presplit_w<<<8192, 256>>>(W_enc);
    presplit_x<<<2048, 256>>>(x);

    // 1) encode GEMM (tf32 hh + bf16 corrections, 512-thread CTA)
    {
        cudaFuncSetAttribute(encode_mma,
                             cudaFuncAttributeMaxDynamicSharedMemorySize, ENC_SMEM);
        dim3 grid(BSZ / BME, LDIM / BNE);   // (32, 128), M-fast for W reuse
        encode_mma<<<grid, ETHREADS, ENC_SMEM>>>(b_enc);
    }

    // 2) top-64 select + zero/scatter z_sparse
    topk_select<<<BSZ, 256>>>(zs);

    // 3) sparse decode
    decode_sparse<<<BSZ, 256>>>(W_dec, b_dec, recon);
}

// round 11
// speedup vs baseline: 1.0883x; 1.0883x over previous
#include <cuda_runtime.h>
#include <cuda_bf16.h>
#include <cstdint>

// x[4096,2048] @ W_enc[2048,16384] + b_enc -> z ; abs-top-64 -> z_sparse ;
// z_sparse @ W_dec[16384,2048] + b_dec -> recon.
// Output: recon [B,D] then z_sparse [B,L], fp32.

#define BSZ   4096
#define DDIM  2048
#define LDIM  16384
#define KSEL  64

// ---------------- scratch (no allocs allowed -> __device__ globals) ----------
__device__ float    g_z[(size_t)BSZ * LDIM];      // dense pre-activation z (256 MB)
__device__ int      g_tidx[BSZ * KSEL];
__device__ float    g_tval[BSZ * KSEL];
// pre-split operands (written once per launch by presplit kernels)
__device__ uint32_t g_whi[(size_t)DDIM * LDIM];           // tf32(w_hi)   128 MB
__device__ uint32_t g_whb[(size_t)(DDIM / 2) * LDIM];     // bf16x2(w_hi)  67 MB
__device__ uint32_t g_wlb[(size_t)(DDIM / 2) * LDIM];     // bf16x2(w_lo)  67 MB
__device__ uint32_t g_xhi[(size_t)BSZ * DDIM];            // tf32(x_hi)
__device__ uint32_t g_xhb[(size_t)BSZ * DDIM / 2];        // bf16x2(x_hi)
__device__ uint32_t g_xlb[(size_t)BSZ * DDIM / 2];        // bf16x2(x_lo)

// ===================== helpers ===============================================
__device__ __forceinline__ uint32_t smem_u32(const void* p) {
    uint32_t a;
    asm("{ .reg .u64 t; cvta.to.shared.u64 t, %1; cvt.u32.u64 %0, t; }"
        : "=r"(a) : "l"(p));
    return a;
}
// hi = round-to-nearest tf32(x); lo = tf32(x - hi). hi+lo error ~2^-24 |x|.
__device__ __forceinline__ void split_tf32(float x, uint32_t& hi, uint32_t& lo) {
    asm("cvt.rna.tf32.f32 %0, %1;" : "=r"(hi) : "f"(x));
    float r = x - __uint_as_float(hi);
    asm("cvt.rna.tf32.f32 %0, %1;" : "=r"(lo) : "f"(r));
}
// pack two floats as bf16x2: low half = f_even (lower k), high = f_odd
__device__ __forceinline__ uint32_t pack_bf16(float f_even, float f_odd) {
    uint32_t r;
    asm("cvt.rn.bf16x2.f32 %0, %1, %2;" : "=r"(r) : "f"(f_odd), "f"(f_even));
    return r;
}
__device__ __forceinline__ void cp16(uint32_t dst, const void* src) {
    asm volatile("cp.async.cg.shared.global [%0], [%1], 16;"
                 :: "r"(dst), "l"(src) : "memory");
}
#define CP_COMMIT() asm volatile("cp.async.commit_group;" ::: "memory")
#define CP_WAIT(n)  asm volatile("cp.async.wait_group %0;" :: "n"(n) : "memory")

#define MMA_TF32(d, a, b)                                                  \
    asm volatile("mma.sync.aligned.m16n8k8.row.col.f32.tf32.tf32.f32 "     \
                 "{%0,%1,%2,%3}, {%4,%5,%6,%7}, {%8,%9}, {%0,%1,%2,%3};"   \
                 : "+f"((d)[0]), "+f"((d)[1]), "+f"((d)[2]), "+f"((d)[3])  \
                 : "r"((a)[0]), "r"((a)[1]), "r"((a)[2]), "r"((a)[3]),     \
                   "r"((b)[0]), "r"((b)[1]))

#define MMA_BF16(d, a, b)                                                  \
    asm volatile("mma.sync.aligned.m16n8k16.row.col.f32.bf16.bf16.f32 "    \
                 "{%0,%1,%2,%3}, {%4,%5,%6,%7}, {%8,%9}, {%0,%1,%2,%3};"   \
                 : "+f"((d)[0]), "+f"((d)[1]), "+f"((d)[2]), "+f"((d)[3])  \
                 : "r"((a)[0]), "r"((a)[1]), "r"((a)[2]), "r"((a)[3]),     \
                   "r"((b)[0]), "r"((b)[1]))

// ===================== pre-split kernels =====================================
__global__ __launch_bounds__(256)
void presplit_w(const float* __restrict__ W) {
    const size_t total = (size_t)(DDIM / 2) * (LDIM / 4);
    const size_t stride = (size_t)gridDim.x * blockDim.x;
    for (size_t idx = (size_t)blockIdx.x * blockDim.x + threadIdx.x;
         idx < total; idx += stride) {
        const size_t kw = idx / (LDIM / 4);
        const size_t nq = idx % (LDIM / 4);
        const size_t n = nq * 4;
        const size_t r0 = (2 * kw) * (size_t)LDIM + n;
        const size_t r1 = r0 + LDIM;
        float4 v0 = *(const float4*)(W + r0);
        float4 v1 = *(const float4*)(W + r1);
        uint4 h0, l0, h1, l1;
        split_tf32(v0.x, h0.x, l0.x); split_tf32(v0.y, h0.y, l0.y);
        split_tf32(v0.z, h0.z, l0.z); split_tf32(v0.w, h0.w, l0.w);
        split_tf32(v1.x, h1.x, l1.x); split_tf32(v1.y, h1.y, l1.y);
        split_tf32(v1.z, h1.z, l1.z); split_tf32(v1.w, h1.w, l1.w);
        *(uint4*)(g_whi + r0) = h0;
        *(uint4*)(g_whi + r1) = h1;
        uint4 hb, lb;
        hb.x = pack_bf16(__uint_as_float(h0.x), __uint_as_float(h1.x));
        hb.y = pack_bf16(__uint_as_float(h0.y), __uint_as_float(h1.y));
        hb.z = pack_bf16(__uint_as_float(h0.z), __uint_as_float(h1.z));
        hb.w = pack_bf16(__uint_as_float(h0.w), __uint_as_float(h1.w));
        lb.x = pack_bf16(__uint_as_float(l0.x), __uint_as_float(l1.x));
        lb.y = pack_bf16(__uint_as_float(l0.y), __uint_as_float(l1.y));
        lb.z = pack_bf16(__uint_as_float(l0.z), __uint_as_float(l1.z));
        lb.w = pack_bf16(__uint_as_float(l0.w), __uint_as_float(l1.w));
        *(uint4*)(g_whb + kw * (size_t)LDIM + n) = hb;
        *(uint4*)(g_wlb + kw * (size_t)LDIM + n) = lb;
    }
}
__global__ __launch_bounds__(256)
void presplit_x(const float* __restrict__ X) {
    const size_t n = (size_t)BSZ * DDIM;
    const size_t stride = (size_t)gridDim.x * blockDim.x * 4;
    for (size_t i = ((size_t)blockIdx.x * blockDim.x + threadIdx.x) * 4;
         i < n; i += stride) {
        float4 v = *(const float4*)(X + i);
        uint4 h, l;
        split_tf32(v.x, h.x, l.x); split_tf32(v.y, h.y, l.y);
        split_tf32(v.z, h.z, l.z); split_tf32(v.w, h.w, l.w);
        *(uint4*)(g_xhi + i) = h;
        uint2 hp, lp;
        hp.x = pack_bf16(__uint_as_float(h.x), __uint_as_float(h.y));
        hp.y = pack_bf16(__uint_as_float(h.z), __uint_as_float(h.w));
        lp.x = pack_bf16(__uint_as_float(l.x), __uint_as_float(l.y));
        lp.y = pack_bf16(__uint_as_float(l.z), __uint_as_float(l.w));
        *(uint2*)(g_xhb + i / 2) = hp;
        *(uint2*)(g_xlb + i / 2) = lp;
    }
}

// ======================= Encode: tf32-hh + bf16 corrections ==================
// R11: back to the R9 shape (256 threads, 8 warps 2m x 4n, warp tile 64x32 --
// crossbar and tensor co-bound at ~2048 cyc/chunk; R10's 16 warps doubled
// B-fragment LDS and went crossbar-bound). New: per-warp software pipelining
// of fragments -- load step i+1's fragments before issuing step i's MMAs so
// LDS latency hides under the same warp's tensor stream (the chunk barrier
// phase-aligns warps, so cross-warp overlap alone was not enough).
// Numerics identical to passing R9: per-chunk zeroed d2, IEEE fold into d.
#define BME 128
#define BNE 128
#define KCE 32
#define NCH (DDIM / KCE)        // 64
// stage layout in 32-bit words
#define O_AH2  0                // tf32 A hi: 4096 w, m*32 + 4*(q^(m&7))
#define O_BH2  4096             // tf32 B hi: 4096 w, kb*128 + 4*(nq^(2*(kb&3)))
#define O_XHB  8192             // bf16 A hi: 128 rows * pitch 20 = 2560 w
#define O_XLB  10752            // bf16 A lo: 2560 w
#define O_WLB  13312            // bf16 B lo: 16*128 = 2048 w, kw*128 + (n^(8*(kw&3)))
#define O_WHB  15360            // bf16 B hi: 2048 w
#define STG_W  17408
#define NSTG 3
#define ENC_SMEM (NSTG * STG_W * 4)   // 208896 bytes
#define APITCH 20

__global__ __launch_bounds__(256, 1)
void encode_mma(const float* __restrict__ bias)  // b_enc [N]
{
    extern __shared__ uint32_t sm[];
    const uint32_t sbase = smem_u32(sm);
    const int tid  = threadIdx.x;
    const int lane = tid & 31, wid = tid >> 5;
    const int wm = wid & 1;          // 0..1 -> m offset 0/64
    const int wn = wid >> 1;         // 0..3 -> n offset 0/32/64/96
    const int g   = lane >> 2;       // 0..7
    const int tig = lane & 3;        // 0..3
    const int m0 = blockIdx.x * BME; // M-fast grid: W tile shared across CTAs
    const int n0 = blockIdx.y * BNE;

    float d[4][4][4];
#pragma unroll
    for (int mi = 0; mi < 4; mi++)
#pragma unroll
        for (int ni = 0; ni < 4; ni++)
#pragma unroll
            for (int q = 0; q < 4; q++) d[mi][ni][q] = 0.0f;

    // ---- issue one chunk's 16 cp.async per thread (256 threads) ----
    auto issue_chunk = [&](int c) {
        const int k0 = c * KCE;
        const int kw0 = c * (KCE / 2);
        const uint32_t st = sbase + (uint32_t)(c % NSTG) * (STG_W * 4);
#pragma unroll
        for (int i = 0; i < 4; i++) {   // tf32 hi tiles: 4 + 4 cp16
            const int gq = tid + 256 * i;
            const int m = gq >> 3, q = gq & 7;
            cp16(st + (uint32_t)(O_AH2 + m * 32 + 4 * (q ^ (m & 7))) * 4,
                 g_xhi + (size_t)(m0 + m) * DDIM + k0 + q * 4);
            const int kb = gq >> 5, nq = gq & 31;
            cp16(st + (uint32_t)(O_BH2 + kb * 128 + 4 * (nq ^ (2 * (kb & 3)))) * 4,
                 g_whi + (size_t)(k0 + kb) * LDIM + n0 + nq * 4);
        }
#pragma unroll
        for (int i = 0; i < 2; i++) {   // bf16 tiles: 2 cp16 each of 4 arrays
            const int gq = tid + 256 * i;          // 0..511
            const int m = gq >> 2, q = gq & 3;
            const uint32_t da = (uint32_t)(m * APITCH + 4 * q);
            const size_t sa = (size_t)(m0 + m) * (DDIM / 2) + kw0 + q * 4;
            cp16(st + (O_XHB + da) * 4, g_xhb + sa);
            cp16(st + (O_XLB + da) * 4, g_xlb + sa);
            const int kw = gq >> 5, nq = gq & 31;
            const uint32_t wo = (uint32_t)(kw * 128 + ((4 * nq) ^ (8 * (kw & 3))));
            const size_t sw = (size_t)(kw0 + kw) * LDIM + n0 + nq * 4;
            cp16(st + (O_WLB + wo) * 4, g_wlb + sw);
            cp16(st + (O_WHB + wo) * 4, g_whb + sw);
        }
    };

    // ---- consumer with per-warp fragment double-buffering ----
    auto mma_chunk = [&](int stg) {
        const int base = stg * STG_W;
        float d2[4][4][4];
#pragma unroll
        for (int mi = 0; mi < 4; mi++)
#pragma unroll
            for (int ni = 0; ni < 4; ni++)
#pragma unroll
                for (int q = 0; q < 4; q++) d2[mi][ni][q] = 0.0f;

        // --- tf32 hh: 4 k8-steps, fragments double-buffered ---
        uint32_t ah[2][4][4], bh[2][4][2];
        auto ld_tf32 = [&](int ks, uint32_t A[4][4], uint32_t B[4][2]) {
            const int x0 = 4 * ((2 * ks) ^ g);
            const int x1 = 4 * ((2 * ks + 1) ^ g);
#pragma unroll
            for (int mi = 0; mi < 4; mi++) {
                const int rb = base + (wm * 64 + mi * 16 + g) * 32 + tig;
                A[mi][0] = sm[O_AH2 + rb + x0];
                A[mi][1] = sm[O_AH2 + rb + 256 + x0];   // row +8
                A[mi][2] = sm[O_AH2 + rb + x1];         // k +4
                A[mi][3] = sm[O_AH2 + rb + 256 + x1];
            }
            const int kk = ks * 8 + tig;
            const int krow = base + kk * 128 + (g & 3);
#pragma unroll
            for (int ni = 0; ni < 4; ni++) {
                const int nsw = 4 * ((wn * 8 + ni * 2 + (g >> 2)) ^ (2 * tig));
                B[ni][0] = sm[O_BH2 + krow + nsw];
                B[ni][1] = sm[O_BH2 + krow + 512 + nsw]; // k +4
            }
        };
        ld_tf32(0, ah[0], bh[0]);
#pragma unroll
        for (int ks = 0; ks < 4; ks++) {
            const int cur = ks & 1, nxt = cur ^ 1;
            if (ks < 3) ld_tf32(ks + 1, ah[nxt], bh[nxt]);
#pragma unroll
            for (int mi = 0; mi < 4; mi++)
#pragma unroll
                for (int ni = 0; ni < 4; ni++)
                    MMA_TF32(d2[mi][ni], ah[cur][mi], bh[cur][ni]);
        }

        // --- bf16 corrections: 2 k16-steps, fragments double-buffered ---
        uint32_t axh[2][4][4], axl[2][4][4], bwl[2][4][2], bwh[2][4][2];
        auto ld_bf16 = [&](int s, uint32_t AH[4][4], uint32_t AL[4][4],
                           uint32_t BL[4][2], uint32_t BH[4][2]) {
            const int kwA0 = 8 * s + tig;
            const int kwA1 = kwA0 + 4;
#pragma unroll
            for (int mi = 0; mi < 4; mi++) {
                const int arow = base + (wm * 64 + mi * 16 + g) * APITCH;
                AH[mi][0] = sm[O_XHB + arow + kwA0];
                AH[mi][1] = sm[O_XHB + arow + 8 * APITCH + kwA0];  // row +8
                AH[mi][2] = sm[O_XHB + arow + kwA1];
                AH[mi][3] = sm[O_XHB + arow + 8 * APITCH + kwA1];
                AL[mi][0] = sm[O_XLB + arow + kwA0];
                AL[mi][1] = sm[O_XLB + arow + 8 * APITCH + kwA0];
                AL[mi][2] = sm[O_XLB + arow + kwA1];
                AL[mi][3] = sm[O_XLB + arow + 8 * APITCH + kwA1];
            }
            const int kwB0 = 8 * s + tig;
            const int kwB1 = kwB0 + 4;
#pragma unroll
            for (int ni = 0; ni < 4; ni++) {
                const int ncol = wn * 32 + ni * 8 + g;
                const int w0 = base + kwB0 * 128 + (ncol ^ (8 * (kwB0 & 3)));
                const int w1 = base + kwB1 * 128 + (ncol ^ (8 * (kwB1 & 3)));
                BL[ni][0] = sm[O_WLB + w0];
                BL[ni][1] = sm[O_WLB + w1];
                BH[ni][0] = sm[O_WHB + w0];
                BH[ni][1] = sm[O_WHB + w1];
            }
        };
        ld_bf16(0, axh[0], axl[0], bwl[0], bwh[0]);
        ld_bf16(1, axh[1], axl[1], bwl[1], bwh[1]);
#pragma unroll
        for (int s = 0; s < 2; s++) {
#pragma unroll
            for (int mi = 0; mi < 4; mi++)
#pragma unroll
                for (int ni = 0; ni < 4; ni++) {
                    MMA_BF16(d2[mi][ni], axh[s][mi], bwl[s][ni]);
                    MMA_BF16(d2[mi][ni], axl[s][mi], bwh[s][ni]);
                }
        }

        // IEEE-RN fold of chunk partial into main accumulator
#pragma unroll
        for (int mi = 0; mi < 4; mi++)
#pragma unroll
            for (int ni = 0; ni < 4; ni++)
#pragma unroll
                for (int q = 0; q < 4; q++)
                    d[mi][ni][q] += d2[mi][ni][q];
    };

    // ---- 3-stage pipeline ----
    issue_chunk(0); CP_COMMIT();
    issue_chunk(1); CP_COMMIT();
    for (int c = 0; c < NCH; c++) {
        if (c + 2 < NCH) { CP_WAIT(1); } else { CP_WAIT(0); }
        __syncthreads();
        if (c + 2 < NCH) { issue_chunk(c + 2); CP_COMMIT(); }
        mma_chunk(c % NSTG);
    }

    // ---- epilogue: add bias, write z ----
#pragma unroll
    for (int ni = 0; ni < 4; ni++) {
        const int col = n0 + wn * 32 + ni * 8 + 2 * tig;
        const float b0 = bias[col], b1 = bias[col + 1];
#pragma unroll
        for (int mi = 0; mi < 4; mi++) {
            const int r0 = m0 + wm * 64 + mi * 16 + g;
            float2 v0 = make_float2(d[mi][ni][0] + b0, d[mi][ni][1] + b1);
            float2 v1 = make_float2(d[mi][ni][2] + b0, d[mi][ni][3] + b1);
            *(float2*)(g_z + (size_t)r0 * LDIM + col) = v0;
            *(float2*)(g_z + (size_t)(r0 + 8) * LDIM + col) = v1;
        }
    }
}

// ---------------- Kernel 2: abs-top-64, threshold-compact + exact radix ------
#define TCAP 2048
#define EQCAP 128

__global__ __launch_bounds__(256)
void topk_select(float* __restrict__ zs_out)
{
    __shared__ uint32_t s_bits[TCAP];
    __shared__ int      s_gidx[TCAP];
    __shared__ unsigned int hist[256];
    __shared__ unsigned int s_cnt, s_prefix, s_remaining, s_cntGT, s_eqcnt;
    __shared__ int   selIdx[KSEL];
    __shared__ float selVal[KSEL];
    __shared__ int   eqPos[EQCAP];

    const int row = blockIdx.x;
    const int tid = threadIdx.x;
    const float* zrow  = g_z    + (size_t)row * LDIM;
    float*       zsrow = zs_out + (size_t)row * LDIM;

    if (tid == 0) s_cnt = 0u;
    __syncthreads();

    const unsigned int T0 = 0x40133333u;   // bits of 2.3f
    for (int i = tid * 4; i < LDIM; i += 1024) {
        float4 v = *(const float4*)(zrow + i);
        *(float4*)(zsrow + i) = make_float4(0.f, 0.f, 0.f, 0.f);
        uint32_t b[4] = {__float_as_uint(v.x), __float_as_uint(v.y),
                         __float_as_uint(v.z), __float_as_uint(v.w)};
#pragma unroll
        for (int j = 0; j < 4; j++) {
            if ((b[j] & 0x7fffffffu) >= T0) {
                unsigned int p = atomicAdd(&s_cnt, 1u);
                if (p < TCAP) { s_bits[p] = b[j]; s_gidx[p] = i + j; }
            }
        }
    }
    __syncthreads();

    const unsigned int C = min(s_cnt, (unsigned int)TCAP);
    bool fallback = (s_cnt < (unsigned int)KSEL) || (s_cnt > (unsigned int)TCAP);
    unsigned int T = 0u, needEQ = 0u;

    if (!fallback) {
        if (tid == 0) { s_prefix = 0u; s_remaining = KSEL; }
        __syncthreads();
#pragma unroll
        for (int pass = 0; pass < 4; pass++) {
            const int shift = 24 - pass * 8;
            if (tid < 256) hist[tid] = 0u;
            __syncthreads();
            const unsigned int pfx = s_prefix;
            for (unsigned int i = tid; i < C; i += 256) {
                unsigned int key = s_bits[i] & 0x7fffffffu;
                bool in = (pass == 0) || ((key >> (shift + 8)) == pfx);
                if (in) atomicAdd(&hist[(key >> shift) & 255u], 1u);
            }
            __syncthreads();
            if (tid == 0) {
                unsigned int cum = 0u; int bkt = 255;
                for (; bkt > 0; bkt--) {
                    unsigned int cc = hist[bkt];
                    if (cum + cc >= s_remaining) break;
                    cum += cc;
                }
                s_prefix = (pfx << 8) | (unsigned int)bkt;
                s_remaining -= cum;
            }
            __syncthreads();
        }
        T = s_prefix; needEQ = s_remaining;

        if (tid == 0) { s_cntGT = 0u; s_eqcnt = 0u; }
        __syncthreads();
        for (unsigned int i = tid; i < C; i += 256) {
            unsigned int key = s_bits[i] & 0x7fffffffu;
            if (key > T) {
                unsigned int p = atomicAdd(&s_cntGT, 1u);
                selIdx[p] = s_gidx[i];
                selVal[p] = __uint_as_float(s_bits[i]);
            } else if (key == T) {
                unsigned int p = atomicAdd(&s_eqcnt, 1u);
                if (p < EQCAP) eqPos[p] = (int)i;
            }
        }
        __syncthreads();
        if (s_eqcnt > (unsigned int)EQCAP) {
            fallback = true;
        } else if (tid == 0) {
            const unsigned int base = s_cntGT;   // == KSEL - needEQ
            const int m = (int)s_eqcnt;
            for (unsigned int t = 0; t < needEQ; t++) {
                int bj = 0, bidx = 0x7fffffff;
                for (int j = 0; j < m; j++) {
                    const int pos = eqPos[j];
                    if (pos >= 0 && s_gidx[pos] < bidx) { bidx = s_gidx[pos]; bj = j; }
                }
                selIdx[base + t] = s_gidx[eqPos[bj]];
                selVal[base + t] = __uint_as_float(s_bits[eqPos[bj]]);
                eqPos[bj] = -1;
            }
        }
        __syncthreads();
    }

    if (fallback) {
        if (tid == 0) { s_prefix = 0u; s_remaining = KSEL; }
        __syncthreads();
#pragma unroll
        for (int pass = 0; pass < 4; pass++) {
            const int shift = 24 - pass * 8;
            if (tid < 256) hist[tid] = 0u;
            __syncthreads();
            const unsigned int pfx = s_prefix;
            for (int i = tid; i < LDIM; i += 256) {
                unsigned int key = __float_as_uint(zrow[i]) & 0x7fffffffu;
                bool in = (pass == 0) || ((key >> (shift + 8)) == pfx);
                if (in) atomicAdd(&hist[(key >> shift) & 255u], 1u);
            }
            __syncthreads();
            if (tid == 0) {
                unsigned int cum = 0u; int bkt = 255;
                for (; bkt > 0; bkt--) {
                    unsigned int cc = hist[bkt];
                    if (cum + cc >= s_remaining) break;
                    cum += cc;
                }
                s_prefix = (pfx << 8) | (unsigned int)bkt;
                s_remaining -= cum;
            }
            __syncthreads();
        }
        T = s_prefix; needEQ = s_remaining;

        if (tid == 0) s_cntGT = 0u;
        __syncthreads();
        for (int i = tid; i < LDIM; i += 256) {
            unsigned int bb = __float_as_uint(zrow[i]);
            unsigned int key = bb & 0x7fffffffu;
            if (key > T) {
                unsigned int p = atomicAdd(&s_cntGT, 1u);
                selIdx[p] = i;
                selVal[p] = __uint_as_float(bb);
            }
        }
        __syncthreads();
        if (tid < 32) {
            const unsigned int base = s_cntGT;
            unsigned int taken = 0u;
            for (int i0 = 0; i0 < LDIM && taken < needEQ; i0 += 32) {
                const int i = i0 + tid;
                unsigned int bb = __float_as_uint(zrow[i]);
                unsigned int key = bb & 0x7fffffffu;
                bool eq = (key == T);
                unsigned int msk = __ballot_sync(0xffffffffu, eq);
                if (eq) {
                    unsigned int rank = __popc(msk & ((1u << tid) - 1u));
                    if (taken + rank < needEQ) {
                        selIdx[base + taken + rank] = i;
                        selVal[base + taken + rank] = __uint_as_float(bb);
                    }
                }
                taken += __popc(msk);
            }
        }
        __syncthreads();
    }

    if (tid < KSEL) {
        zsrow[selIdx[tid]] = selVal[tid];
        g_tidx[row * KSEL + tid] = selIdx[tid];
        g_tval[row * KSEL + tid] = selVal[tid];
    }
}

// ---------------- Kernel 3: sparse decode ------------------------------------
__global__ __launch_bounds__(256)
void decode_sparse(const float* __restrict__ Wd,
                   const float* __restrict__ bd,
                   float* __restrict__ recon)
{
    __shared__ int   sIdx[KSEL];
    __shared__ float sVal[KSEL];
    const int row = blockIdx.x;
    const int tid = threadIdx.x;
    if (tid < KSEL) {
        sIdx[tid] = g_tidx[row * KSEL + tid];
        sVal[tid] = g_tval[row * KSEL + tid];
    }
    __syncthreads();

    const int c0 = tid * 4;
    const int c1 = (tid + 256) * 4;
    float4 a0 = *(const float4*)(bd + c0);
    float4 a1 = *(const float4*)(bd + c1);

#pragma unroll 4
    for (int j = 0; j < KSEL; j++) {
        const float v = sVal[j];
        const float* wr = Wd + (size_t)sIdx[j] * DDIM;
        float4 w0 = *(const float4*)(wr + c0);
        float4 w1 = *(const float4*)(wr + c1);
        a0.x = fmaf(v, w0.x, a0.x); a0.y = fmaf(v, w0.y, a0.y);
        a0.z = fmaf(v, w0.z, a0.z); a0.w = fmaf(v, w0.w, a0.w);
        a1.x = fmaf(v, w1.x, a1.x); a1.y = fmaf(v, w1.y, a1.y);
        a1.z = fmaf(v, w1.z, a1.z); a1.w = fmaf(v, w1.w, a1.w);
    }
    float* r = recon + (size_t)row * DDIM;
    *(float4*)(r + c0) = a0;
    *(float4*)(r + c1) = a1;
}

// ---------------- launch ------------------------------------------------------
extern "C" void kernel_launch(void* const* d_in, const int* in_sizes, int n_in,
                              void* d_out, int out_size)
{
    const float* x     = (const float*)d_in[0];   // [B, D]
    const float* W_enc = (const float*)d_in[1];   // [D, L]
    const float* b_enc = (const float*)d_in[2];   // [L]
    const float* W_dec = (const float*)d_in[3];   // [L, D]
    const float* b_dec = (const float*)d_in[4];   // [D]
    (void)in_sizes; (void)n_in; (void)out_size;

    float* recon = (float*)d_out;                          // [B, D]
    float* zs    = (float*)d_out + (size_t)BSZ * DDIM;     // [B, L]

    // 0) one-time operand pre-split (~90us)
    presplit_w<<<8192, 256>>>(W_enc);
    presplit_x<<<2048, 256>>>(x);

    // 1) encode GEMM (tf32 hh + bf16 corrections, 256 threads, frag pipelined)
    {
        cudaFuncSetAttribute(encode_mma,
                             cudaFuncAttributeMaxDynamicSharedMemorySize, ENC_SMEM);
        dim3 grid(BSZ / BME, LDIM / BNE);   // (32, 128), M-fast for W reuse
        encode_mma<<<grid, 256, ENC_SMEM>>>(b_enc);
    }

    // 2) top-64 select + zero/scatter z_sparse
    topk_select<<<BSZ, 256>>>(zs);

    // 3) sparse decode
    decode_sparse<<<BSZ, 256>>>(W_dec, b_dec, recon);
}